// round 3
// baseline (speedup 1.0000x reference)
#include <cuda_runtime.h>

// Problem constants
#define G_     2
#define BATCH_ 128
#define L_     2048
#define SD_    64
#define ID_    16
#define OD_    16
#define C_     128           // chunks per sequence
#define T_     (L_/C_)       // 16 steps per chunk

// ---------- device scratch (no allocations allowed) ----------
__device__ float g_FT[G_*SD_*SD_];                        // F^16 per group
__device__ float g_d[(size_t)G_*BATCH_*L_*SD_];           // precolored drive, [gb][l][64]
__device__ float g_lend[(size_t)G_*BATCH_*C_*SD_];        // local chunk-end states
__device__ float g_carry[(size_t)G_*BATCH_*C_*SD_];       // true incoming state per chunk

// ---------- f32x2 packed helpers ----------
__device__ __forceinline__ unsigned long long pack2(float lo, float hi) {
    unsigned long long r;
    asm("mov.b64 %0, {%1, %2};" : "=l"(r) : "f"(lo), "f"(hi));
    return r;
}
__device__ __forceinline__ void unpack2(unsigned long long v, float& lo, float& hi) {
    asm("mov.b64 {%0, %1}, %2;" : "=f"(lo), "=f"(hi) : "l"(v));
}
__device__ __forceinline__ void fma2(unsigned long long& acc, unsigned long long a, unsigned long long b) {
    asm("fma.rn.f32x2 %0, %1, %2, %0;" : "+l"(acc) : "l"(a), "l"(b));
}

// 64-wide dot: acc over 64 floats in smem (broadcast) vs 32 packed regs
__device__ __forceinline__ float dot64(const unsigned long long* m2,
                                       const float* vec_sh, float init) {
    unsigned long long a0=0ULL, a1=0ULL, a2=0ULL, a3=0ULL;
    const ulonglong2* sp = (const ulonglong2*)vec_sh;
    #pragma unroll
    for (int i = 0; i < 16; i += 2) {
        ulonglong2 va = sp[i], vb = sp[i+1];
        fma2(a0, m2[2*i],   va.x);
        fma2(a1, m2[2*i+1], va.y);
        fma2(a2, m2[2*i+2], vb.x);
        fma2(a3, m2[2*i+3], vb.y);
    }
    float x0,x1,y0,y1,z0,z1,u0,u1;
    unpack2(a0,x0,x1); unpack2(a1,y0,y1); unpack2(a2,z0,z1); unpack2(a3,u0,u1);
    return init + (((x0+x1)+(y0+y1)) + ((z0+z1)+(u0+u1)));
}

// load a 64-float global row into 32 packed regs
__device__ __forceinline__ void load_row64(unsigned long long* m2, const float* row) {
    const float4* r4 = (const float4*)row;
    #pragma unroll
    for (int i = 0; i < 16; i++) {
        float4 v = r4[i];
        m2[2*i]   = pack2(v.x, v.y);
        m2[2*i+1] = pack2(v.z, v.w);
    }
}

// ============================================================================
// K_pow: FT = F^16 via 4 squarings. grid = G_, 512 threads.
// ============================================================================
__global__ void __launch_bounds__(512) power_kernel(const float* __restrict__ Fm) {
    __shared__ float A[SD_*SD_];
    __shared__ float Bb[SD_*SD_];
    const int g = blockIdx.x, tid = threadIdx.x;
    for (int i = tid; i < SD_*SD_; i += 512) A[i] = Fm[g*SD_*SD_ + i];
    __syncthreads();
    const int r  = tid >> 3;
    const int cq = (tid & 7) * 8;
    #pragma unroll
    for (int it = 0; it < 4; it++) {       // F^2, F^4, F^8, F^16
        const float* src = (it & 1) ? Bb : A;
        float*       dst = (it & 1) ? A  : Bb;
        float acc[8];
        #pragma unroll
        for (int j = 0; j < 8; j++) acc[j] = 0.f;
        for (int k = 0; k < SD_; k++) {
            float a = src[r*SD_ + k];
            #pragma unroll
            for (int j = 0; j < 8; j++) acc[j] += a * src[k*SD_ + cq + j];
        }
        __syncthreads();
        #pragma unroll
        for (int j = 0; j < 8; j++) dst[r*SD_ + cq + j] = acc[j];
        __syncthreads();
    }
    // after 4 iterations result is in A
    for (int i = tid; i < SD_*SD_; i += 512) g_FT[g*SD_*SD_ + i] = A[i];
}

// ============================================================================
// P1: precolor drive d[gb][l][:] = SW_g * w[l] + B_g * u[l].
// grid = GB * (L/64), block = 256 (4 subgroups of 64; subgroup sg does 16 l's)
// ============================================================================
__global__ void __launch_bounds__(256)
precolor_kernel(const float* __restrict__ wn, const float* __restrict__ inputs,
                const float* __restrict__ SW, const float* __restrict__ Bm)
{
    __shared__ __align__(16) float w_sh[64][SD_];
    __shared__ __align__(16) float u_sh[64][ID_];
    const int tid = threadIdx.x;
    const int lt  = blockIdx.x & 31;           // L_/64 = 32 tiles
    const int gb  = blockIdx.x >> 5;
    const int g   = gb / BATCH_;
    const int l0  = lt * 64;
    const int t   = tid & 63;
    const int sg  = tid >> 6;

    unsigned long long sw2[32], b2[8];
    load_row64(sw2, SW + ((size_t)g*SD_ + t)*SD_);
    {
        const float4* Brow = (const float4*)(Bm + ((size_t)g*SD_ + t)*ID_);
        #pragma unroll
        for (int i = 0; i < 4; i++) {
            float4 v = Brow[i];
            b2[2*i] = pack2(v.x, v.y); b2[2*i+1] = pack2(v.z, v.w);
        }
    }

    // cooperative tile loads (coalesced float4)
    {
        const int r = tid >> 2, qd = tid & 3;   // 64 rows, 4 threads/row
        const float4* src = (const float4*)(wn + ((size_t)(l0 + r)*(G_*BATCH_) + gb)*SD_) + qd*4;
        float4* dst = (float4*)(&w_sh[r][0]) + qd*4;
        #pragma unroll
        for (int i = 0; i < 4; i++) dst[i] = src[i];
        const float4* usrc = (const float4*)(inputs + ((size_t)gb*L_ + l0 + r)*ID_) + qd;
        ((float4*)(&u_sh[r][0]))[qd] = usrc[0];
    }
    __syncthreads();

    float* dbase = g_d + ((size_t)gb*L_ + l0)*SD_;
    #pragma unroll
    for (int j = 0; j < 16; j++) {
        const int l = sg*16 + j;
        unsigned long long a0=0ULL, a1=0ULL, a2=0ULL, a3=0ULL;
        const ulonglong2* wp = (const ulonglong2*)w_sh[l];
        #pragma unroll
        for (int i = 0; i < 16; i += 2) {
            ulonglong2 va = wp[i], vb = wp[i+1];
            fma2(a0, sw2[2*i],   va.x);
            fma2(a1, sw2[2*i+1], va.y);
            fma2(a2, sw2[2*i+2], vb.x);
            fma2(a3, sw2[2*i+3], vb.y);
        }
        const ulonglong2* up = (const ulonglong2*)u_sh[l];
        #pragma unroll
        for (int i = 0; i < 4; i += 2) {
            ulonglong2 va = up[i], vb = up[i+1];
            fma2(a0, b2[2*i],   va.x);
            fma2(a1, b2[2*i+1], va.y);
            fma2(a2, b2[2*i+2], vb.x);
            fma2(a3, b2[2*i+3], vb.y);
        }
        float x0,x1,y0,y1,z0,z1,u0,u1;
        unpack2(a0,x0,x1); unpack2(a1,y0,y1); unpack2(a2,z0,z1); unpack2(a3,u0,u1);
        dbase[(size_t)l*SD_ + t] = (((x0+x1)+(y0+y1)) + ((z0+z1)+(u0+u1)));
    }
}

// ============================================================================
// A: chunk-local scan, chunk-end only. grid = GB*C_, block = 64.
// s starts at true state (chunk 0) or zero; 1 barrier/step, F-matvec only.
// ============================================================================
__global__ void __launch_bounds__(64)
scanA_kernel(const float* __restrict__ state, const float* __restrict__ Fm)
{
    const int t  = threadIdx.x;
    const int c  = blockIdx.x & (C_-1);
    const int gb = blockIdx.x >> 7;            // C_ = 128
    const int g  = gb / BATCH_;
    __shared__ __align__(16) float s_sh[2][SD_];

    unsigned long long f2v[32];
    load_row64(f2v, Fm + ((size_t)g*SD_ + t)*SD_);

    float d_pf[T_];
    const float* dbase = g_d + ((size_t)gb*L_ + c*T_)*SD_ + t;
    #pragma unroll
    for (int k = 0; k < T_; k++) d_pf[k] = dbase[(size_t)k*SD_];

    s_sh[0][t] = (c == 0) ? state[(size_t)gb*SD_ + t] : 0.f;
    __syncthreads();

    float sval = 0.f;
    #pragma unroll
    for (int k = 0; k < T_; k++) {
        const int pb = k & 1;
        sval = dot64(f2v, s_sh[pb], d_pf[k]);
        s_sh[pb^1][t] = sval;
        __syncthreads();
    }
    g_lend[((size_t)gb*C_ + c)*SD_ + t] = sval;
}

// ============================================================================
// carry: serial propagation of chunk-end states via F^16. grid = GB, block 64.
// te(c) = lend(c) + FT * te(c-1);  carry(c) = te(c-1)
// ============================================================================
__global__ void __launch_bounds__(64) carry_kernel()
{
    const int t = threadIdx.x, gb = blockIdx.x, g = gb / BATCH_;
    __shared__ __align__(16) float te_sh[SD_];

    unsigned long long ft2[32];
    load_row64(ft2, g_FT + ((size_t)g*SD_ + t)*SD_);

    const float* lend = g_lend + (size_t)gb*C_*SD_;
    float* carry = g_carry + (size_t)gb*C_*SD_;

    float te = lend[t];                     // true end of chunk 0
    float le_next = lend[SD_ + t];          // lend(1)
    for (int c = 1; c < C_; c++) {
        carry[(size_t)c*SD_ + t] = te;
        te_sh[t] = te;
        float le = le_next;
        if (c + 1 < C_) le_next = lend[(size_t)(c+1)*SD_ + t];
        __syncthreads();
        te = dot64(ft2, te_sh, le);
        __syncthreads();
    }
}

// ============================================================================
// B: true scan with correct carry; writes all states. grid = GB*C_, block 64.
// ============================================================================
__global__ void __launch_bounds__(64)
scanB_kernel(const float* __restrict__ state, const float* __restrict__ Fm,
             float* __restrict__ states_out)
{
    const int t  = threadIdx.x;
    const int c  = blockIdx.x & (C_-1);
    const int gb = blockIdx.x >> 7;
    const int g  = gb / BATCH_;
    __shared__ __align__(16) float s_sh[2][SD_];

    unsigned long long f2v[32];
    load_row64(f2v, Fm + ((size_t)g*SD_ + t)*SD_);

    float d_pf[T_];
    const float* dbase = g_d + ((size_t)gb*L_ + c*T_)*SD_ + t;
    #pragma unroll
    for (int k = 0; k < T_; k++) d_pf[k] = dbase[(size_t)k*SD_];

    s_sh[0][t] = (c == 0) ? state[(size_t)gb*SD_ + t]
                          : g_carry[((size_t)gb*C_ + c)*SD_ + t];
    __syncthreads();

    float* st_out = states_out + ((size_t)gb*L_ + c*T_)*SD_ + t;
    #pragma unroll
    for (int k = 0; k < T_; k++) {
        const int pb = k & 1;
        float sval = dot64(f2v, s_sh[pb], d_pf[k]);
        st_out[(size_t)k*SD_] = sval;          // coalesced, off critical path
        s_sh[pb^1][t] = sval;
        __syncthreads();
    }
}

// ============================================================================
// P4: observations o[l] = H_g * s[l] + SV_g * v[l].
// grid = GB * (L/128), block = 256. 40KB+pad smem tile of states + v.
// ============================================================================
__global__ void __launch_bounds__(256)
obs_kernel(const float* __restrict__ Hm, const float* __restrict__ SV,
           const float* __restrict__ vn, const float* __restrict__ states_out,
           float* __restrict__ obs_out)
{
    __shared__ __align__(16) float s_sh[128][SD_ + 4];   // +4 pad: kill bank conflicts
    __shared__ __align__(16) float v_sh[128][OD_];
    const int tid = threadIdx.x;
    const int lt  = blockIdx.x & 15;         // L_/128 = 16 tiles
    const int gb  = blockIdx.x >> 4;
    const int g   = gb / BATCH_;
    const int l0  = lt * 128;
    const int p   = tid & 15;

    unsigned long long h2[32], sv2[8];
    load_row64(h2, Hm + ((size_t)g*OD_ + p)*SD_);
    {
        const float4* SVrow = (const float4*)(SV + ((size_t)g*OD_ + p)*OD_);
        #pragma unroll
        for (int i = 0; i < 4; i++) {
            float4 v = SVrow[i];
            sv2[2*i] = pack2(v.x, v.y); sv2[2*i+1] = pack2(v.z, v.w);
        }
    }

    // cooperative tile loads
    {
        const int r = tid >> 1, half = tid & 1;   // 128 rows, 2 threads/row
        const float4* src = (const float4*)(states_out + ((size_t)gb*L_ + l0 + r)*SD_) + half*8;
        float4* dst = (float4*)(&s_sh[r][0]) + half*8;
        #pragma unroll
        for (int i = 0; i < 8; i++) dst[i] = src[i];
        const float4* vsrc = (const float4*)(vn + ((size_t)(l0 + r)*(G_*BATCH_) + gb)*OD_) + half*2;
        float4* vdst = (float4*)(&v_sh[r][0]) + half*2;
        vdst[0] = vsrc[0]; vdst[1] = vsrc[1];
    }
    __syncthreads();

    const int lq = (tid >> 4) & 3;
    const int sg = tid >> 6;
    float* obase = obs_out + ((size_t)gb*L_ + l0)*OD_;
    #pragma unroll
    for (int j = 0; j < 8; j++) {
        const int l = sg*32 + j*4 + lq;
        unsigned long long a0=0ULL, a1=0ULL, a2=0ULL, a3=0ULL;
        const ulonglong2* sp = (const ulonglong2*)(&s_sh[l][0]);
        #pragma unroll
        for (int i = 0; i < 16; i += 2) {
            ulonglong2 va = sp[i], vb = sp[i+1];
            fma2(a0, h2[2*i],   va.x);
            fma2(a1, h2[2*i+1], va.y);
            fma2(a2, h2[2*i+2], vb.x);
            fma2(a3, h2[2*i+3], vb.y);
        }
        const ulonglong2* vp = (const ulonglong2*)(&v_sh[l][0]);
        #pragma unroll
        for (int i = 0; i < 4; i += 2) {
            ulonglong2 va = vp[i], vb = vp[i+1];
            fma2(a0, sv2[2*i],   va.x);
            fma2(a1, sv2[2*i+1], va.y);
            fma2(a2, sv2[2*i+2], vb.x);
            fma2(a3, sv2[2*i+3], vb.y);
        }
        float x0,x1,y0,y1,z0,z1,u0,u1;
        unpack2(a0,x0,x1); unpack2(a1,y0,y1); unpack2(a2,z0,z1); unpack2(a3,u0,u1);
        obase[(size_t)l*OD_ + p] = (((x0+x1)+(y0+y1)) + ((z0+z1)+(u0+u1)));
    }
}

// ============================================================================
extern "C" void kernel_launch(void* const* d_in, const int* in_sizes, int n_in,
                              void* d_out, int out_size) {
    const float* state  = (const float*)d_in[0];   // [G,B,S]
    const float* inputs = (const float*)d_in[1];   // [G,B,L,I]
    const float* Fm     = (const float*)d_in[2];   // [G,S,S]
    const float* Bm     = (const float*)d_in[3];   // [G,S,I]
    const float* Hm     = (const float*)d_in[4];   // [G,O,S]
    const float* SW     = (const float*)d_in[5];   // [G,S,S]
    const float* SV     = (const float*)d_in[6];   // [G,O,O]
    const float* wn     = (const float*)d_in[7];   // [L,G,B,S]
    const float* vn     = (const float*)d_in[8];   // [L,G,B,O]

    float* states_out = (float*)d_out;                           // [G,B,L,S]
    float* obs_out    = states_out + (size_t)G_*BATCH_*L_*SD_;   // [G,B,L,O]

    const int GB = G_*BATCH_;

    power_kernel   <<<G_, 512>>>(Fm);
    precolor_kernel<<<GB*32, 256>>>(wn, inputs, SW, Bm);
    scanA_kernel   <<<GB*C_, 64>>>(state, Fm);
    carry_kernel   <<<GB, 64>>>();
    scanB_kernel   <<<GB*C_, 64>>>(state, Fm, states_out);
    obs_kernel     <<<GB*16, 256>>>(Hm, SV, vn, states_out, obs_out);
}

// round 4
// speedup vs baseline: 1.3404x; 1.3404x over previous
#include <cuda_runtime.h>

// Problem constants
#define G_     2
#define BATCH_ 128
#define L_     2048
#define SD_    64
#define ID_    16
#define OD_    16

// ---------- device scratch (no allocations allowed) ----------
__device__ float g_d[(size_t)G_*BATCH_*L_*SD_];   // precolored drive, [gb][l][64]

// ---------- f32x2 packed helpers ----------
__device__ __forceinline__ unsigned long long pack2(float lo, float hi) {
    unsigned long long r;
    asm("mov.b64 %0, {%1, %2};" : "=l"(r) : "f"(lo), "f"(hi));
    return r;
}
__device__ __forceinline__ void unpack2(unsigned long long v, float& lo, float& hi) {
    asm("mov.b64 {%0, %1}, %2;" : "=f"(lo), "=f"(hi) : "l"(v));
}
__device__ __forceinline__ void fma2(unsigned long long& acc, unsigned long long a, unsigned long long b) {
    asm("fma.rn.f32x2 %0, %1, %2, %0;" : "+l"(acc) : "l"(a), "l"(b));
}

// 64-wide dot: 64 floats in smem (broadcast) vs 32 packed regs, + init
__device__ __forceinline__ float dot64(const unsigned long long* m2,
                                       const float* vec_sh, float init) {
    unsigned long long a0=0ULL, a1=0ULL, a2=0ULL, a3=0ULL;
    const ulonglong2* sp = (const ulonglong2*)vec_sh;
    #pragma unroll
    for (int i = 0; i < 16; i += 2) {
        ulonglong2 va = sp[i], vb = sp[i+1];
        fma2(a0, m2[2*i],   va.x);
        fma2(a1, m2[2*i+1], va.y);
        fma2(a2, m2[2*i+2], vb.x);
        fma2(a3, m2[2*i+3], vb.y);
    }
    float x0,x1,y0,y1,z0,z1,u0,u1;
    unpack2(a0,x0,x1); unpack2(a1,y0,y1); unpack2(a2,z0,z1); unpack2(a3,u0,u1);
    return init + (((x0+x1)+(y0+y1)) + ((z0+z1)+(u0+u1)));
}

// load a 64-float global row into 32 packed regs
__device__ __forceinline__ void load_row64(unsigned long long* m2, const float* row) {
    const float4* r4 = (const float4*)row;
    #pragma unroll
    for (int i = 0; i < 16; i++) {
        float4 v = r4[i];
        m2[2*i]   = pack2(v.x, v.y);
        m2[2*i+1] = pack2(v.z, v.w);
    }
}

// ============================================================================
// P1: precolor drive d[gb][l][:] = SW_g * w[l] + B_g * u[l].
// grid = GB * (L/64), block = 256 (4 subgroups of 64; subgroup sg does 16 l's)
// ============================================================================
__global__ void __launch_bounds__(256)
precolor_kernel(const float* __restrict__ wn, const float* __restrict__ inputs,
                const float* __restrict__ SW, const float* __restrict__ Bm)
{
    __shared__ __align__(16) float w_sh[64][SD_];
    __shared__ __align__(16) float u_sh[64][ID_];
    const int tid = threadIdx.x;
    const int lt  = blockIdx.x & 31;           // L_/64 = 32 tiles
    const int gb  = blockIdx.x >> 5;
    const int g   = gb / BATCH_;
    const int l0  = lt * 64;
    const int t   = tid & 63;
    const int sg  = tid >> 6;

    unsigned long long sw2[32], b2[8];
    load_row64(sw2, SW + ((size_t)g*SD_ + t)*SD_);
    {
        const float4* Brow = (const float4*)(Bm + ((size_t)g*SD_ + t)*ID_);
        #pragma unroll
        for (int i = 0; i < 4; i++) {
            float4 v = Brow[i];
            b2[2*i] = pack2(v.x, v.y); b2[2*i+1] = pack2(v.z, v.w);
        }
    }

    // cooperative tile loads (coalesced float4)
    {
        const int r = tid >> 2, qd = tid & 3;   // 64 rows, 4 threads/row
        const float4* src = (const float4*)(wn + ((size_t)(l0 + r)*(G_*BATCH_) + gb)*SD_) + qd*4;
        float4* dst = (float4*)(&w_sh[r][0]) + qd*4;
        #pragma unroll
        for (int i = 0; i < 4; i++) dst[i] = src[i];
        const float4* usrc = (const float4*)(inputs + ((size_t)gb*L_ + l0 + r)*ID_) + qd;
        ((float4*)(&u_sh[r][0]))[qd] = usrc[0];
    }
    __syncthreads();

    float* dbase = g_d + ((size_t)gb*L_ + l0)*SD_;
    #pragma unroll
    for (int j = 0; j < 16; j++) {
        const int l = sg*16 + j;
        unsigned long long a0=0ULL, a1=0ULL, a2=0ULL, a3=0ULL;
        const ulonglong2* wp = (const ulonglong2*)w_sh[l];
        #pragma unroll
        for (int i = 0; i < 16; i += 2) {
            ulonglong2 va = wp[i], vb = wp[i+1];
            fma2(a0, sw2[2*i],   va.x);
            fma2(a1, sw2[2*i+1], va.y);
            fma2(a2, sw2[2*i+2], vb.x);
            fma2(a3, sw2[2*i+3], vb.y);
        }
        const ulonglong2* up = (const ulonglong2*)u_sh[l];
        #pragma unroll
        for (int i = 0; i < 4; i += 2) {
            ulonglong2 va = up[i], vb = up[i+1];
            fma2(a0, b2[2*i],   va.x);
            fma2(a1, b2[2*i+1], va.y);
            fma2(a2, b2[2*i+2], vb.x);
            fma2(a3, b2[2*i+3], vb.y);
        }
        float x0,x1,y0,y1,z0,z1,u0,u1;
        unpack2(a0,x0,x1); unpack2(a1,y0,y1); unpack2(a2,z0,z1); unpack2(a3,u0,u1);
        dbase[(size_t)l*SD_ + t] = (((x0+x1)+(y0+y1)) + ((z0+z1)+(u0+u1)));
    }
}

// ============================================================================
// SCAN: the only serial kernel. grid = GB (256), block = 64.
// Per step: s[t] = F[t,:]·s + d_l[t]; one barrier; drive prefetched 8 ahead.
// ============================================================================
__global__ void __launch_bounds__(64)
scan_kernel(const float* __restrict__ state, const float* __restrict__ Fm,
            float* __restrict__ states_out)
{
    const int t  = threadIdx.x;
    const int gb = blockIdx.x;
    const int g  = gb / BATCH_;

    __shared__ __align__(16) float s_sh[2][SD_];

    unsigned long long f2v[32];
    load_row64(f2v, Fm + ((size_t)g*SD_ + t)*SD_);

    const float* dbase  = g_d + (size_t)gb*L_*SD_ + t;
    float*       st_out = states_out + (size_t)gb*L_*SD_ + t;

    // prefetch ring, depth 8
    float ring[8];
    #pragma unroll
    for (int j = 0; j < 8; j++) ring[j] = dbase[(size_t)j*SD_];

    s_sh[0][t] = state[(size_t)gb*SD_ + t];
    __syncthreads();

    #pragma unroll 8
    for (int k = 0; k < L_; k++) {
        const int pb = k & 1;
        const float dval = ring[k & 7];
        if (k + 8 < L_) ring[k & 7] = dbase[(size_t)(k + 8)*SD_];

        const float sval = dot64(f2v, s_sh[pb], dval);

        s_sh[pb ^ 1][t] = sval;
        st_out[(size_t)k*SD_] = sval;       // coalesced, off critical path
        __syncthreads();
    }
}

// ============================================================================
// P4: observations o[l] = H_g * s[l] + SV_g * v[l].
// grid = GB * (L/128), block = 256.
// ============================================================================
__global__ void __launch_bounds__(256)
obs_kernel(const float* __restrict__ Hm, const float* __restrict__ SV,
           const float* __restrict__ vn, const float* __restrict__ states_out,
           float* __restrict__ obs_out)
{
    __shared__ __align__(16) float s_sh[128][SD_ + 4];   // +4 pad: kill bank conflicts
    __shared__ __align__(16) float v_sh[128][OD_];
    const int tid = threadIdx.x;
    const int lt  = blockIdx.x & 15;         // L_/128 = 16 tiles
    const int gb  = blockIdx.x >> 4;
    const int g   = gb / BATCH_;
    const int l0  = lt * 128;
    const int p   = tid & 15;

    unsigned long long h2[32], sv2[8];
    load_row64(h2, Hm + ((size_t)g*OD_ + p)*SD_);
    {
        const float4* SVrow = (const float4*)(SV + ((size_t)g*OD_ + p)*OD_);
        #pragma unroll
        for (int i = 0; i < 4; i++) {
            float4 v = SVrow[i];
            sv2[2*i] = pack2(v.x, v.y); sv2[2*i+1] = pack2(v.z, v.w);
        }
    }

    // cooperative tile loads
    {
        const int r = tid >> 1, half = tid & 1;   // 128 rows, 2 threads/row
        const float4* src = (const float4*)(states_out + ((size_t)gb*L_ + l0 + r)*SD_) + half*8;
        float4* dst = (float4*)(&s_sh[r][0]) + half*8;
        #pragma unroll
        for (int i = 0; i < 8; i++) dst[i] = src[i];
        const float4* vsrc = (const float4*)(vn + ((size_t)(l0 + r)*(G_*BATCH_) + gb)*OD_) + half*2;
        float4* vdst = (float4*)(&v_sh[r][0]) + half*2;
        vdst[0] = vsrc[0]; vdst[1] = vsrc[1];
    }
    __syncthreads();

    const int lq = (tid >> 4) & 3;
    const int sg = tid >> 6;
    float* obase = obs_out + ((size_t)gb*L_ + l0)*OD_;
    #pragma unroll
    for (int j = 0; j < 8; j++) {
        const int l = sg*32 + j*4 + lq;
        unsigned long long a0=0ULL, a1=0ULL, a2=0ULL, a3=0ULL;
        const ulonglong2* sp = (const ulonglong2*)(&s_sh[l][0]);
        #pragma unroll
        for (int i = 0; i < 16; i += 2) {
            ulonglong2 va = sp[i], vb = sp[i+1];
            fma2(a0, h2[2*i],   va.x);
            fma2(a1, h2[2*i+1], va.y);
            fma2(a2, h2[2*i+2], vb.x);
            fma2(a3, h2[2*i+3], vb.y);
        }
        const ulonglong2* vp = (const ulonglong2*)(&v_sh[l][0]);
        #pragma unroll
        for (int i = 0; i < 4; i += 2) {
            ulonglong2 va = vp[i], vb = vp[i+1];
            fma2(a0, sv2[2*i],   va.x);
            fma2(a1, sv2[2*i+1], va.y);
            fma2(a2, sv2[2*i+2], vb.x);
            fma2(a3, sv2[2*i+3], vb.y);
        }
        float x0,x1,y0,y1,z0,z1,u0,u1;
        unpack2(a0,x0,x1); unpack2(a1,y0,y1); unpack2(a2,z0,z1); unpack2(a3,u0,u1);
        obase[(size_t)l*OD_ + p] = (((x0+x1)+(y0+y1)) + ((z0+z1)+(u0+u1)));
    }
}

// ============================================================================
extern "C" void kernel_launch(void* const* d_in, const int* in_sizes, int n_in,
                              void* d_out, int out_size) {
    const float* state  = (const float*)d_in[0];   // [G,B,S]
    const float* inputs = (const float*)d_in[1];   // [G,B,L,I]
    const float* Fm     = (const float*)d_in[2];   // [G,S,S]
    const float* Bm     = (const float*)d_in[3];   // [G,S,I]
    const float* Hm     = (const float*)d_in[4];   // [G,O,S]
    const float* SW     = (const float*)d_in[5];   // [G,S,S]
    const float* SV     = (const float*)d_in[6];   // [G,O,O]
    const float* wn     = (const float*)d_in[7];   // [L,G,B,S]
    const float* vn     = (const float*)d_in[8];   // [L,G,B,O]

    float* states_out = (float*)d_out;                           // [G,B,L,S]
    float* obs_out    = states_out + (size_t)G_*BATCH_*L_*SD_;   // [G,B,L,O]

    const int GB = G_*BATCH_;

    precolor_kernel<<<GB*32, 256>>>(wn, inputs, SW, Bm);
    scan_kernel    <<<GB, 64>>>(state, Fm, states_out);
    obs_kernel     <<<GB*16, 256>>>(Hm, SV, vn, states_out, obs_out);
}

// round 5
// speedup vs baseline: 1.6796x; 1.2530x over previous
#include <cuda_runtime.h>

// Problem constants
#define G_     2
#define BATCH_ 128
#define L_     2048
#define SD_    64
#define ID_    16
#define OD_    16
#define GB_    (G_*BATCH_)

// ---------- device scratch (no allocations allowed) ----------
// +8 rows of padding so the scan's branchless ring prefetch never faults
__device__ float g_d[(size_t)GB_*L_*SD_ + 8*SD_];

// ---------- f32x2 packed helpers ----------
__device__ __forceinline__ unsigned long long pack2(float lo, float hi) {
    unsigned long long r;
    asm("mov.b64 %0, {%1, %2};" : "=l"(r) : "f"(lo), "f"(hi));
    return r;
}
__device__ __forceinline__ void unpack2(unsigned long long v, float& lo, float& hi) {
    asm("mov.b64 {%0, %1}, %2;" : "=f"(lo), "=f"(hi) : "l"(v));
}
__device__ __forceinline__ void fma2(unsigned long long& acc, unsigned long long a, unsigned long long b) {
    asm("fma.rn.f32x2 %0, %1, %2, %0;" : "+l"(acc) : "l"(a), "l"(b));
}
__device__ __forceinline__ void add2(unsigned long long& d, unsigned long long a, unsigned long long b) {
    asm("add.rn.f32x2 %0, %1, %2;" : "=l"(d) : "l"(a), "l"(b));
}

// load a 64-float global row into 32 packed regs (pairs along the row)
__device__ __forceinline__ void load_row64(unsigned long long* m2, const float* row) {
    const float4* r4 = (const float4*)row;
    #pragma unroll
    for (int i = 0; i < 16; i++) {
        float4 v = r4[i];
        m2[2*i]   = pack2(v.x, v.y);
        m2[2*i+1] = pack2(v.z, v.w);
    }
}

// ============================================================================
// P1: precolor tiled GEMM. d[dim][l] = sum_k SWB[dim][k] * wu[k][l].
// Block: one gb, 64 l's. 64 threads; thread = (dg: 8 dims) x (lg: 8 l's).
// K = 80 (64 w-dims + 16 u-dims). Dims packed in f32x2 (a-pairs from LDS.128).
// ============================================================================
__global__ void __launch_bounds__(64)
precolor_kernel(const float* __restrict__ wn, const float* __restrict__ inputs,
                const float* __restrict__ SW, const float* __restrict__ Bm)
{
    __shared__ __align__(16) float wT[80][68];     // [k][l]  (w rows 0..63, u rows 64..79)
    __shared__ __align__(16) float SWBt[80][64];   // [k][dim] (SW rows 0..63, B rows 64..79)

    const int tid = threadIdx.x;
    const int lt  = blockIdx.x & 31;           // 32 l-tiles
    const int gb  = blockIdx.x >> 5;
    const int g   = gb / BATCH_;
    const int l0  = lt * 64;

    // ---- stage transposed operand panels (each thread owns one l-row / dim-row) ----
    {
        const float4* wrow = (const float4*)(wn + ((size_t)(l0 + tid)*GB_ + gb)*SD_);
        #pragma unroll
        for (int i = 0; i < 16; i++) {
            float4 v = wrow[i];
            wT[4*i  ][tid] = v.x; wT[4*i+1][tid] = v.y;
            wT[4*i+2][tid] = v.z; wT[4*i+3][tid] = v.w;
        }
        const float4* urow = (const float4*)(inputs + ((size_t)gb*L_ + l0 + tid)*ID_);
        #pragma unroll
        for (int i = 0; i < 4; i++) {
            float4 v = urow[i];
            wT[64+4*i  ][tid] = v.x; wT[64+4*i+1][tid] = v.y;
            wT[64+4*i+2][tid] = v.z; wT[64+4*i+3][tid] = v.w;
        }
        const float4* swrow = (const float4*)(SW + ((size_t)g*SD_ + tid)*SD_);
        #pragma unroll
        for (int i = 0; i < 16; i++) {
            float4 v = swrow[i];
            SWBt[4*i  ][tid] = v.x; SWBt[4*i+1][tid] = v.y;
            SWBt[4*i+2][tid] = v.z; SWBt[4*i+3][tid] = v.w;
        }
        const float4* brow = (const float4*)(Bm + ((size_t)g*SD_ + tid)*ID_);
        #pragma unroll
        for (int i = 0; i < 4; i++) {
            float4 v = brow[i];
            SWBt[64+4*i  ][tid] = v.x; SWBt[64+4*i+1][tid] = v.y;
            SWBt[64+4*i+2][tid] = v.z; SWBt[64+4*i+3][tid] = v.w;
        }
    }
    __syncthreads();

    const int dg = tid >> 3;   // dims [dg*8, dg*8+8)
    const int lg = tid & 7;    // l's  [lg*8, lg*8+8)

    unsigned long long acc[4][8];   // [dim-pair][l]
    #pragma unroll
    for (int p = 0; p < 4; p++)
        #pragma unroll
        for (int j = 0; j < 8; j++) acc[p][j] = 0ULL;

    #pragma unroll 4
    for (int k = 0; k < 80; k++) {
        const ulonglong2* ap = (const ulonglong2*)&SWBt[k][dg*8];
        ulonglong2 a01 = ap[0], a23 = ap[1];          // 4 dim-pairs
        const float* bp = &wT[k][lg*8];
        #pragma unroll
        for (int j = 0; j < 8; j++) {
            unsigned long long bd = pack2(bp[j], bp[j]);
            fma2(acc[0][j], a01.x, bd);
            fma2(acc[1][j], a01.y, bd);
            fma2(acc[2][j], a23.x, bd);
            fma2(acc[3][j], a23.y, bd);
        }
    }

    // ---- write out: per l, 8 consecutive dims = 2 STG.128 ----
    float* dbase = g_d + ((size_t)gb*L_ + l0 + lg*8)*SD_ + dg*8;
    #pragma unroll
    for (int j = 0; j < 8; j++) {
        float d0,d1,d2,d3,d4,d5,d6,d7;
        unpack2(acc[0][j], d0, d1);
        unpack2(acc[1][j], d2, d3);
        unpack2(acc[2][j], d4, d5);
        unpack2(acc[3][j], d6, d7);
        float4* out = (float4*)(dbase + (size_t)j*SD_);
        out[0] = make_float4(d0, d1, d2, d3);
        out[1] = make_float4(d4, d5, d6, d7);
    }
}

// ============================================================================
// SCAN: the only serial kernel. grid = GB (256), block = 64.
// Per step: s[t] = F[t,:]*s + d_l[t]; one barrier; drive prefetched 8 ahead.
// ============================================================================
__global__ void __launch_bounds__(64)
scan_kernel(const float* __restrict__ state, const float* __restrict__ Fm,
            float* __restrict__ states_out)
{
    const int t  = threadIdx.x;
    const int gb = blockIdx.x;
    const int g  = gb / BATCH_;

    __shared__ __align__(16) float s_sh[2][SD_];

    unsigned long long f2v[32];
    load_row64(f2v, Fm + ((size_t)g*SD_ + t)*SD_);

    const float* dbase  = g_d + (size_t)gb*L_*SD_ + t;
    float*       st_out = states_out + (size_t)gb*L_*SD_ + t;

    // prefetch ring, depth 8 (branchless: g_d is padded)
    float ring[8];
    #pragma unroll
    for (int j = 0; j < 8; j++) ring[j] = dbase[(size_t)j*SD_];

    s_sh[0][t] = state[(size_t)gb*SD_ + t];
    __syncthreads();

    #pragma unroll 8
    for (int k = 0; k < L_; k++) {
        const int pb = k & 1;
        const float dval = ring[k & 7];
        ring[k & 7] = dbase[(size_t)(k + 8)*SD_];   // beyond-L reads land in pad, never used

        // dot64 with packed-add reduce
        unsigned long long a0=0ULL, a1=0ULL, a2=0ULL, a3=0ULL;
        const ulonglong2* sp = (const ulonglong2*)s_sh[pb];
        #pragma unroll
        for (int i = 0; i < 16; i += 2) {
            ulonglong2 va = sp[i], vb = sp[i+1];
            fma2(a0, f2v[2*i],   va.x);
            fma2(a1, f2v[2*i+1], va.y);
            fma2(a2, f2v[2*i+2], vb.x);
            fma2(a3, f2v[2*i+3], vb.y);
        }
        add2(a0, a0, a1);
        add2(a2, a2, a3);
        add2(a0, a0, a2);
        float lo, hi; unpack2(a0, lo, hi);
        const float sval = dval + lo + hi;

        s_sh[pb ^ 1][t] = sval;
        st_out[(size_t)k*SD_] = sval;               // coalesced, off critical path
        __syncthreads();
    }
}

// ============================================================================
// P4: obs tiled GEMM. o[p][l] = sum_k HSV[p][k] * sv[k][l], K=80 (64 s + 16 v).
// Block: one gb, 128 l's. 64 threads; thread = (dg: 4 dims) x (lg: 8 l's).
// ============================================================================
__global__ void __launch_bounds__(64)
obs_kernel(const float* __restrict__ Hm, const float* __restrict__ SV,
           const float* __restrict__ vn, const float* __restrict__ states_out,
           float* __restrict__ obs_out)
{
    __shared__ __align__(16) float xT[80][132];    // [k][l]: s rows 0..63, v rows 64..79
    __shared__ __align__(16) float HSVt[80][16];   // [k][p]

    const int tid = threadIdx.x;
    const int lt  = blockIdx.x & 15;          // 16 l-tiles of 128
    const int gb  = blockIdx.x >> 4;
    const int g   = gb / BATCH_;
    const int l0  = lt * 128;

    // ---- stage: each thread transposes 2 l-rows of states + v ----
    #pragma unroll
    for (int rr = 0; rr < 2; rr++) {
        const int r = tid + rr*64;
        const float4* srow = (const float4*)(states_out + ((size_t)gb*L_ + l0 + r)*SD_);
        #pragma unroll
        for (int i = 0; i < 16; i++) {
            float4 v = srow[i];
            xT[4*i  ][r] = v.x; xT[4*i+1][r] = v.y;
            xT[4*i+2][r] = v.z; xT[4*i+3][r] = v.w;
        }
        const float4* vrow = (const float4*)(vn + ((size_t)(l0 + r)*GB_ + gb)*OD_);
        #pragma unroll
        for (int i = 0; i < 4; i++) {
            float4 v = vrow[i];
            xT[64+4*i  ][r] = v.x; xT[64+4*i+1][r] = v.y;
            xT[64+4*i+2][r] = v.z; xT[64+4*i+3][r] = v.w;
        }
    }
    if (tid < 16) {
        const float4* hrow = (const float4*)(Hm + ((size_t)g*OD_ + tid)*SD_);
        #pragma unroll
        for (int i = 0; i < 16; i++) {
            float4 v = hrow[i];
            HSVt[4*i  ][tid] = v.x; HSVt[4*i+1][tid] = v.y;
            HSVt[4*i+2][tid] = v.z; HSVt[4*i+3][tid] = v.w;
        }
        const float4* svrow = (const float4*)(SV + ((size_t)g*OD_ + tid)*OD_);
        #pragma unroll
        for (int i = 0; i < 4; i++) {
            float4 v = svrow[i];
            HSVt[64+4*i  ][tid] = v.x; HSVt[64+4*i+1][tid] = v.y;
            HSVt[64+4*i+2][tid] = v.z; HSVt[64+4*i+3][tid] = v.w;
        }
    }
    __syncthreads();

    const int dg = tid >> 4;    // dims [dg*4, dg*4+4)
    const int lg = tid & 15;    // l's  [lg*8, lg*8+8)

    unsigned long long acc[2][8];   // [dim-pair][l]
    #pragma unroll
    for (int p = 0; p < 2; p++)
        #pragma unroll
        for (int j = 0; j < 8; j++) acc[p][j] = 0ULL;

    #pragma unroll 4
    for (int k = 0; k < 80; k++) {
        const ulonglong2* ap = (const ulonglong2*)&HSVt[k][dg*4];
        ulonglong2 a01 = ap[0];                       // 2 dim-pairs
        const float* bp = &xT[k][lg*8];
        #pragma unroll
        for (int j = 0; j < 8; j++) {
            unsigned long long bd = pack2(bp[j], bp[j]);
            fma2(acc[0][j], a01.x, bd);
            fma2(acc[1][j], a01.y, bd);
        }
    }

    float* obase = obs_out + ((size_t)gb*L_ + l0 + lg*8)*OD_ + dg*4;
    #pragma unroll
    for (int j = 0; j < 8; j++) {
        float o0,o1,o2,o3;
        unpack2(acc[0][j], o0, o1);
        unpack2(acc[1][j], o2, o3);
        *(float4*)(obase + (size_t)j*OD_) = make_float4(o0, o1, o2, o3);
    }
}

// ============================================================================
extern "C" void kernel_launch(void* const* d_in, const int* in_sizes, int n_in,
                              void* d_out, int out_size) {
    const float* state  = (const float*)d_in[0];   // [G,B,S]
    const float* inputs = (const float*)d_in[1];   // [G,B,L,I]
    const float* Fm     = (const float*)d_in[2];   // [G,S,S]
    const float* Bm     = (const float*)d_in[3];   // [G,S,I]
    const float* Hm     = (const float*)d_in[4];   // [G,O,S]
    const float* SW     = (const float*)d_in[5];   // [G,S,S]
    const float* SV     = (const float*)d_in[6];   // [G,O,O]
    const float* wn     = (const float*)d_in[7];   // [L,G,B,S]
    const float* vn     = (const float*)d_in[8];   // [L,G,B,O]

    float* states_out = (float*)d_out;                           // [G,B,L,S]
    float* obs_out    = states_out + (size_t)GB_*L_*SD_;         // [G,B,L,O]

    precolor_kernel<<<GB_*32, 64>>>(wn, inputs, SW, Bm);
    scan_kernel    <<<GB_, 64>>>(state, Fm, states_out);
    obs_kernel     <<<GB_*16, 64>>>(Hm, SV, vn, states_out, obs_out);
}